// round 3
// baseline (speedup 1.0000x reference)
#include <cuda_runtime.h>
#include <cstdint>

// Problem constants (fixed shapes)
#define BATCH   4
#define SEQL    4096
#define DMODEL  2048
#define HALF    32
#define N2      64                 // 2*HALF (re || im)
#define MTOT    (BATCH*SEQL)       // 16384
#define CHUNK   64                 // scan chunk length
#define NCHUNK  (SEQL/CHUNK)       // 64 chunks per batch
#define TILEK   32

typedef unsigned long long ull;

// ---------------- scratch (static device globals; no allocation) ----------------
__device__ float g_W1[DMODEL * N2];        // folded B_bar weights [d][j]   (512 KB)
__device__ float g_W2[N2 * DMODEL];        // folded C weights [j][d]       (512 KB)
__device__ float g_Bu[MTOT * N2];          // Bu, then xs in-place          (4 MB)
__device__ float g_carry[BATCH * NCHUNK * N2];
__device__ float g_pref [BATCH * NCHUNK * N2];
// params: [0:32) lb_re, [32:64) lb_im, [64:96) lbS_re, [96:128) lbS_im,
//         [128:160) s_re, [160:192) s_im
__device__ float g_par[192];

// ---------------- f32x2 helpers ----------------
__device__ __forceinline__ ull fma2(ull a, ull b, ull c) {
    ull d;
    asm("fma.rn.f32x2 %0, %1, %2, %3;" : "=l"(d) : "l"(a), "l"(b), "l"(c));
    return d;
}

// ---------------- setup: per-state parameters ----------------
__global__ void k_params(const float* __restrict__ Lur,
                         const float* __restrict__ Lim,
                         const float* __restrict__ logD) {
    int n = threadIdx.x;
    if (n >= HALF) return;
    float x   = Lur[n];
    float sp  = (x > 20.f) ? x : log1pf(expf(x));
    float lre = -(sp + 1e-4f + 0.01f);
    float lim = Lim[n];
    float dt  = expf(logD[n]);
    float ar = lre * dt, ai = lim * dt;
    float er = expf(ar);
    float lbr = er * cosf(ai);
    float lbi = er * sinf(ai);
    // s = (lam_bar - 1) / lam   (complex)
    float den = lre * lre + lim * lim;
    float nr = lbr - 1.f, ni = lbi;
    float sre = (nr * lre + ni * lim) / den;
    float sim = (ni * lre - nr * lim) / den;
    // lam_bar^CHUNK = exp(CHUNK * lam * dt)
    float er64 = expf((float)CHUNK * ar);
    float a64  = (float)CHUNK * ai;
    float lbSr = er64 * cosf(a64);
    float lbSi = er64 * sinf(a64);
    g_par[n]       = lbr;  g_par[32 + n]  = lbi;
    g_par[64 + n]  = lbSr; g_par[96 + n]  = lbSi;
    g_par[128 + n] = sre;  g_par[160 + n] = sim;
}

// W1[d][j]: j<32 -> re part of s*B_tilde;  j>=32 -> im part
__global__ void k_w1(const float* __restrict__ Bre, const float* __restrict__ Bim) {
    for (int idx = blockIdx.x * blockDim.x + threadIdx.x; idx < DMODEL * N2;
         idx += gridDim.x * blockDim.x) {
        int d = idx >> 6;
        int j = idx & 63;
        int n = j & 31;
        float sre = g_par[128 + n], sim = g_par[160 + n];
        float br = Bre[n * DMODEL + d], bi = Bim[n * DMODEL + d];
        g_W1[idx] = (j < 32) ? (sre * br - sim * bi) : (sre * bi + sim * br);
    }
}

// W2[j][d]: j<32 -> 2*C_re[d][j];  j>=32 -> -2*C_im[d][j-32]
__global__ void k_w2(const float* __restrict__ Cre, const float* __restrict__ Cim) {
    for (int idx = blockIdx.x * blockDim.x + threadIdx.x; idx < N2 * DMODEL;
         idx += gridDim.x * blockDim.x) {
        int j = idx >> 11;          // / DMODEL
        int d = idx & 2047;
        g_W2[idx] = (j < 32) ? (2.f * Cre[d * HALF + j])
                             : (-2.f * Cim[d * HALF + (j - 32)]);
    }
}

// ---------------- GEMM1: Bu[m][j] = sum_d u[m][d] * W1[d][j] ----------------
// 256 threads, BM=128, BN=64, K-tile=32.
// f32x2 pairs span TWO M-ROWS (LDS64 from [k][m] tile); W duplicated (w,w) in smem.
// Inner loop per k: 4 LDS64(u) + 4 LDS64(wdup) + 16 fma2 -> 67% fma share.
__global__ __launch_bounds__(256) void k_gemm1(const float* __restrict__ u) {
    __shared__ __align__(16) float su[TILEK * 130];   // [k][m], pad 130
    __shared__ __align__(16) float swd[TILEK * 128];  // [k][col*2] duplicated pairs
    int tid = threadIdx.x;
    int tx = tid & 15;          // col group: cols tx + 16*cc, cc<4
    int ty = tid >> 4;          // 0..15: row pairs 2*ty + 32*j, j<4
    int m0 = blockIdx.x * 128;

    ull acc[4][4];
    #pragma unroll
    for (int j = 0; j < 4; ++j)
        #pragma unroll
        for (int c = 0; c < 4; ++c) acc[j][c] = 0ull;

    float4 ru[4], rw[2];
    // prologue: load tile 0 into registers
    #pragma unroll
    for (int t = 0; t < 4; ++t) {
        int idx = tid + 256 * t;
        int ro = idx >> 3, c4 = idx & 7;
        ru[t] = *(const float4*)(u + (size_t)(m0 + ro) * DMODEL + c4 * 4);
    }
    #pragma unroll
    for (int t = 0; t < 2; ++t) {
        int idx = tid + 256 * t;
        int ro = idx >> 4, c4 = idx & 15;
        rw[t] = *(const float4*)(g_W1 + ro * 64 + c4 * 4);
    }

    for (int kt = 0; kt < DMODEL / TILEK; ++kt) {
        __syncthreads();
        // STS staged tile (u transposed [k][m]; w duplicated)
        #pragma unroll
        for (int t = 0; t < 4; ++t) {
            int idx = tid + 256 * t;
            int ro = idx >> 3, c4 = idx & 7;
            su[(c4 * 4 + 0) * 130 + ro] = ru[t].x;
            su[(c4 * 4 + 1) * 130 + ro] = ru[t].y;
            su[(c4 * 4 + 2) * 130 + ro] = ru[t].z;
            su[(c4 * 4 + 3) * 130 + ro] = ru[t].w;
        }
        #pragma unroll
        for (int t = 0; t < 2; ++t) {
            int idx = tid + 256 * t;
            int ro = idx >> 4, c4 = idx & 15;
            float2* dst = (float2*)(swd + ro * 128 + c4 * 8);
            dst[0] = make_float2(rw[t].x, rw[t].x);
            dst[1] = make_float2(rw[t].y, rw[t].y);
            dst[2] = make_float2(rw[t].z, rw[t].z);
            dst[3] = make_float2(rw[t].w, rw[t].w);
        }
        __syncthreads();
        // prefetch next tile (LDG in flight during compute)
        if (kt + 1 < DMODEL / TILEK) {
            int kb = (kt + 1) * TILEK;
            #pragma unroll
            for (int t = 0; t < 4; ++t) {
                int idx = tid + 256 * t;
                int ro = idx >> 3, c4 = idx & 7;
                ru[t] = *(const float4*)(u + (size_t)(m0 + ro) * DMODEL + kb + c4 * 4);
            }
            #pragma unroll
            for (int t = 0; t < 2; ++t) {
                int idx = tid + 256 * t;
                int ro = idx >> 4, c4 = idx & 15;
                rw[t] = *(const float4*)(g_W1 + (kb + ro) * 64 + c4 * 4);
            }
        }
        // compute
        #pragma unroll
        for (int k = 0; k < TILEK; ++k) {
            ull up[4], wp[4];
            #pragma unroll
            for (int j = 0; j < 4; ++j)
                up[j] = *(const ull*)(su + k * 130 + 2 * ty + 32 * j);
            #pragma unroll
            for (int c = 0; c < 4; ++c)
                wp[c] = *(const ull*)(swd + k * 128 + (tx + 16 * c) * 2);
            #pragma unroll
            for (int j = 0; j < 4; ++j)
                #pragma unroll
                for (int c = 0; c < 4; ++c)
                    acc[j][c] = fma2(up[j], wp[c], acc[j][c]);
        }
    }
    // store: each ull = (row, row+1) for one col
    #pragma unroll
    for (int j = 0; j < 4; ++j) {
        int r0 = m0 + 2 * ty + 32 * j;
        #pragma unroll
        for (int c = 0; c < 4; ++c) {
            int col = tx + 16 * c;
            float2 f = *reinterpret_cast<float2*>(&acc[j][c]);
            g_Bu[(size_t)r0 * N2 + col]       = f.x;
            g_Bu[(size_t)(r0 + 1) * N2 + col] = f.y;
        }
    }
}

// ---------------- scan phase 1: per-chunk local recurrence ----------------
__global__ void k_scan_local() {
    int w = (blockIdx.x * blockDim.x + threadIdx.x) >> 5;
    int lane = threadIdx.x & 31;
    int b = w >> 6, c = w & (NCHUNK - 1);
    float lbr = g_par[lane], lbi = g_par[32 + lane];
    float xr = 0.f, xi = 0.f;
    size_t base = ((size_t)b * SEQL + (size_t)c * CHUNK) * N2;
    for (int i = 0; i < CHUNK; ++i) {
        size_t off = base + (size_t)i * N2;
        float br = g_Bu[off + lane];
        float bi = g_Bu[off + 32 + lane];
        float nr = fmaf(lbr, xr, fmaf(-lbi, xi, br));
        float ni = fmaf(lbr, xi, fmaf( lbi, xr, bi));
        g_Bu[off + lane]      = nr;
        g_Bu[off + 32 + lane] = ni;
        xr = nr; xi = ni;
    }
    int co = (b * NCHUNK + c) * N2;
    g_carry[co + lane] = xr;
    g_carry[co + 32 + lane] = xi;
}

// ---------------- scan phase 2: chunk-carry prefix (exclusive) ----------------
__global__ void k_scan_prefix() {
    int w = threadIdx.x >> 5;     // b
    int lane = threadIdx.x & 31;
    float lbSr = g_par[64 + lane], lbSi = g_par[96 + lane];
    float Pr = 0.f, Pi = 0.f;
    for (int c = 0; c < NCHUNK; ++c) {
        int o = (w * NCHUNK + c) * N2;
        g_pref[o + lane] = Pr;
        g_pref[o + 32 + lane] = Pi;
        float cr = g_carry[o + lane];
        float ci = g_carry[o + 32 + lane];
        float nr = fmaf(lbSr, Pr, fmaf(-lbSi, Pi, cr));
        float ni = fmaf(lbSr, Pi, fmaf( lbSi, Pr, ci));
        Pr = nr; Pi = ni;
    }
}

// ---------------- scan phase 3: fixup x[l] += lam^(i+1) * P ----------------
__global__ void k_scan_fix() {
    int w = (blockIdx.x * blockDim.x + threadIdx.x) >> 5;
    int lane = threadIdx.x & 31;
    int b = w >> 6, c = w & (NCHUNK - 1);
    float lbr = g_par[lane], lbi = g_par[32 + lane];
    int po = (b * NCHUNK + c) * N2;
    float Pr = g_pref[po + lane], Pi = g_pref[po + 32 + lane];
    float pr = lbr, pi = lbi;    // lam_bar^(i+1), i = 0
    size_t base = ((size_t)b * SEQL + (size_t)c * CHUNK) * N2;
    for (int i = 0; i < CHUNK; ++i) {
        size_t off = base + (size_t)i * N2;
        float ar = pr * Pr - pi * Pi;
        float ai = pr * Pi + pi * Pr;
        g_Bu[off + lane]      += ar;
        g_Bu[off + 32 + lane] += ai;
        float npr = pr * lbr - pi * lbi;
        float npi = pr * lbi + pi * lbr;
        pr = npr; pi = npi;
    }
}

// ---------------- GEMM2: y[m][d] = X[m][:] @ W2[:,d] + D[d]*u[m][d] ----------------
// 256 threads, BM=128, BN=64, K=64 single tile. Same row-pair f32x2 scheme.
// Dynamic smem: sx [64][130] + swd [64][128] = 66048 bytes.
extern __shared__ float g2_smem[];
__global__ __launch_bounds__(256) void k_gemm2(const float* __restrict__ u,
                                               const float* __restrict__ Dv,
                                               float* __restrict__ y) {
    float* sx  = g2_smem;              // [k][m] pad 130 : 64*130
    float* swd = g2_smem + 64 * 130;   // [k][col*2]     : 64*128
    int tid = threadIdx.x;
    int tx = tid & 15;
    int ty = tid >> 4;
    int n0 = blockIdx.x * 64;
    int m0 = blockIdx.y * 128;

    if (tid < 128) {
        // load X row (m0+tid), scatter transposed (conflict-free: bank = 2k+row)
        #pragma unroll
        for (int t = 0; t < 16; ++t) {
            float4 v = *(const float4*)(g_Bu + (size_t)(m0 + tid) * N2 + t * 4);
            sx[(t * 4 + 0) * 130 + tid] = v.x;
            sx[(t * 4 + 1) * 130 + tid] = v.y;
            sx[(t * 4 + 2) * 130 + tid] = v.z;
            sx[(t * 4 + 3) * 130 + tid] = v.w;
        }
    } else {
        int id = tid - 128;
        #pragma unroll
        for (int t = 0; t < 8; ++t) {
            int idx = id + 128 * t;
            int ro = idx >> 4, c4 = idx & 15;
            float4 v = *(const float4*)(g_W2 + (size_t)ro * DMODEL + n0 + c4 * 4);
            float2* dst = (float2*)(swd + ro * 128 + c4 * 8);
            dst[0] = make_float2(v.x, v.x);
            dst[1] = make_float2(v.y, v.y);
            dst[2] = make_float2(v.z, v.z);
            dst[3] = make_float2(v.w, v.w);
        }
    }
    __syncthreads();

    ull acc[4][4];
    #pragma unroll
    for (int j = 0; j < 4; ++j)
        #pragma unroll
        for (int c = 0; c < 4; ++c) acc[j][c] = 0ull;

    #pragma unroll 8
    for (int k = 0; k < 64; ++k) {
        ull up[4], wp[4];
        #pragma unroll
        for (int j = 0; j < 4; ++j)
            up[j] = *(const ull*)(sx + k * 130 + 2 * ty + 32 * j);
        #pragma unroll
        for (int c = 0; c < 4; ++c)
            wp[c] = *(const ull*)(swd + k * 128 + (tx + 16 * c) * 2);
        #pragma unroll
        for (int j = 0; j < 4; ++j)
            #pragma unroll
            for (int c = 0; c < 4; ++c)
                acc[j][c] = fma2(up[j], wp[c], acc[j][c]);
    }

    // epilogue: + D * u, scalar writes (lanes tx consecutive -> coalesced 64B)
    float dreg[4];
    #pragma unroll
    for (int c = 0; c < 4; ++c) dreg[c] = Dv[n0 + tx + 16 * c];
    #pragma unroll
    for (int j = 0; j < 4; ++j) {
        int r0 = m0 + 2 * ty + 32 * j;
        #pragma unroll
        for (int c = 0; c < 4; ++c) {
            int col = n0 + tx + 16 * c;
            float2 f = *reinterpret_cast<float2*>(&acc[j][c]);
            size_t o0 = (size_t)r0 * DMODEL + col;
            size_t o1 = o0 + DMODEL;
            y[o0] = f.x + dreg[c] * u[o0];
            y[o1] = f.y + dreg[c] * u[o1];
        }
    }
}

// ---------------- launch ----------------
extern "C" void kernel_launch(void* const* d_in, const int* in_sizes, int n_in,
                              void* d_out, int out_size) {
    const float* u    = (const float*)d_in[0];
    const float* Lur  = (const float*)d_in[1];
    const float* Lim  = (const float*)d_in[2];
    const float* Bre  = (const float*)d_in[3];
    const float* Bim  = (const float*)d_in[4];
    const float* Cre  = (const float*)d_in[5];
    const float* Cim  = (const float*)d_in[6];
    const float* Dv   = (const float*)d_in[7];
    const float* logD = (const float*)d_in[8];
    float* y = (float*)d_out;

    const int g2_bytes = (64 * 130 + 64 * 128) * 4;   // 66048
    cudaFuncSetAttribute(k_gemm2, cudaFuncAttributeMaxDynamicSharedMemorySize,
                         g2_bytes);

    k_params<<<1, 32>>>(Lur, Lim, logD);
    k_w1<<<128, 256>>>(Bre, Bim);
    k_w2<<<128, 256>>>(Cre, Cim);
    k_gemm1<<<MTOT / 128, 256>>>(u);
    k_scan_local<<<(BATCH * NCHUNK) / 4, 128>>>();
    k_scan_prefix<<<1, BATCH * 32>>>();
    k_scan_fix<<<(BATCH * NCHUNK) / 4, 128>>>();
    k_gemm2<<<dim3(DMODEL / 64, MTOT / 128), 256, g2_bytes>>>(u, Dv, y);
}

// round 5
// speedup vs baseline: 1.9589x; 1.9589x over previous
#include <cuda_runtime.h>
#include <cuda_bf16.h>
#include <cstdint>

#define BATCH   4
#define SEQL    4096
#define DMODEL  2048
#define HALF    32
#define N2      64
#define MTOT    (BATCH*SEQL)
#define CHUNK   64
#define NCHUNK  (SEQL/CHUNK)

// ---------------- scratch ----------------
__device__ __nv_bfloat16 g_W1h[N2 * DMODEL];   // [j][d]  B operand of GEMM1 (row=n, col=k)
__device__ __nv_bfloat16 g_W1l[N2 * DMODEL];
__device__ __nv_bfloat16 g_W2h[DMODEL * N2];   // [d][j]  B operand of GEMM2 (row=n, col=k)
__device__ __nv_bfloat16 g_W2l[DMODEL * N2];
__device__ float g_Bu[MTOT * N2];
__device__ float g_carry[BATCH * NCHUNK * N2];
__device__ float g_pref [BATCH * NCHUNK * N2];
__device__ float g_par[192];

// ---------------- helpers ----------------
__device__ __forceinline__ void cvt_hl(float x, uint16_t& h, uint16_t& l) {
    __nv_bfloat16 hb = __float2bfloat16_rn(x);
    float r = x - __bfloat162float(hb);
    __nv_bfloat16 lb = __float2bfloat16_rn(r);
    h = *(uint16_t*)&hb;
    l = *(uint16_t*)&lb;
}

// pack 8 floats -> 8 bf16 hi (uint4) + 8 bf16 lo (uint4)
__device__ __forceinline__ void cvt8(const float4& v0, const float4& v1,
                                     uint4& h, uint4& l) {
    uint16_t hh[8], ll[8];
    cvt_hl(v0.x, hh[0], ll[0]); cvt_hl(v0.y, hh[1], ll[1]);
    cvt_hl(v0.z, hh[2], ll[2]); cvt_hl(v0.w, hh[3], ll[3]);
    cvt_hl(v1.x, hh[4], ll[4]); cvt_hl(v1.y, hh[5], ll[5]);
    cvt_hl(v1.z, hh[6], ll[6]); cvt_hl(v1.w, hh[7], ll[7]);
    h = make_uint4((uint32_t)hh[0] | ((uint32_t)hh[1] << 16),
                   (uint32_t)hh[2] | ((uint32_t)hh[3] << 16),
                   (uint32_t)hh[4] | ((uint32_t)hh[5] << 16),
                   (uint32_t)hh[6] | ((uint32_t)hh[7] << 16));
    l = make_uint4((uint32_t)ll[0] | ((uint32_t)ll[1] << 16),
                   (uint32_t)ll[2] | ((uint32_t)ll[3] << 16),
                   (uint32_t)ll[4] | ((uint32_t)ll[5] << 16),
                   (uint32_t)ll[6] | ((uint32_t)ll[7] << 16));
}

// mma.sync m16n8k16 bf16 (sm_80+ plain PTX -> HMMA on sm_103)
__device__ __forceinline__ void mma16816(float* c, const uint32_t* a,
                                         const uint32_t* b) {
    asm volatile(
        "mma.sync.aligned.m16n8k16.row.col.f32.bf16.bf16.f32 "
        "{%0,%1,%2,%3}, {%4,%5,%6,%7}, {%8,%9}, {%0,%1,%2,%3};"
        : "+f"(c[0]), "+f"(c[1]), "+f"(c[2]), "+f"(c[3])
        : "r"(a[0]), "r"(a[1]), "r"(a[2]), "r"(a[3]), "r"(b[0]), "r"(b[1]));
}

// Smem panel layout: panel kp (8 k-values), entry = 16B (8 bf16) per row.
// byte offset = kp*rowcount*16 + (row ^ kp)*16   (XOR swizzle, kp<8)
// A panels: 128 rows (2048 B/panel). B panels: 64 rows (1024 B/panel).
#define A_PANEL 2048
#define B_PANEL 1024
#define OFF_AH 0
#define OFF_AL 16384
#define OFF_BH 32768
#define OFF_BL 40960
#define SMEM_BYTES 49152

// load A fragment (4 regs) for k16 starting at panel p, row base rb
__device__ __forceinline__ void ldA(const char* base, int p, int rb, int g,
                                    int tig, uint32_t* a) {
    const char* q0 = base + p * A_PANEL;
    const char* q1 = base + (p + 1) * A_PANEL;
    int x0 = p & 7, x1 = (p + 1) & 7;
    a[0] = *(const uint32_t*)(q0 + ((rb + g)     ^ x0) * 16 + tig * 4);
    a[1] = *(const uint32_t*)(q0 + ((rb + g + 8) ^ x0) * 16 + tig * 4);
    a[2] = *(const uint32_t*)(q1 + ((rb + g)     ^ x1) * 16 + tig * 4);
    a[3] = *(const uint32_t*)(q1 + ((rb + g + 8) ^ x1) * 16 + tig * 4);
}
__device__ __forceinline__ void ldB(const char* base, int p, int nb, int g,
                                    int tig, uint32_t* b) {
    b[0] = *(const uint32_t*)(base + p * B_PANEL
                              + ((nb + g) ^ (p & 7)) * 16 + tig * 4);
    b[1] = *(const uint32_t*)(base + (p + 1) * B_PANEL
                              + ((nb + g) ^ ((p + 1) & 7)) * 16 + tig * 4);
}

// ---------------- setup: per-state parameters ----------------
__global__ void k_params(const float* __restrict__ Lur,
                         const float* __restrict__ Lim,
                         const float* __restrict__ logD) {
    int n = threadIdx.x;
    if (n >= HALF) return;
    float x   = Lur[n];
    float sp  = (x > 20.f) ? x : log1pf(expf(x));
    float lre = -(sp + 1e-4f + 0.01f);
    float lim = Lim[n];
    float dt  = expf(logD[n]);
    float ar = lre * dt, ai = lim * dt;
    float er = expf(ar);
    float lbr = er * cosf(ai);
    float lbi = er * sinf(ai);
    float den = lre * lre + lim * lim;
    float nr = lbr - 1.f, ni = lbi;
    float sre = (nr * lre + ni * lim) / den;
    float sim = (ni * lre - nr * lim) / den;
    float er64 = expf((float)CHUNK * ar);
    float a64  = (float)CHUNK * ai;
    float lbSr = er64 * cosf(a64);
    float lbSi = er64 * sinf(a64);
    g_par[n]       = lbr;  g_par[32 + n]  = lbi;
    g_par[64 + n]  = lbSr; g_par[96 + n]  = lbSi;
    g_par[128 + n] = sre;  g_par[160 + n] = sim;
}

// g_W1h/l [j][d]
__global__ void k_w1(const float* __restrict__ Bre, const float* __restrict__ Bim) {
    for (int idx = blockIdx.x * blockDim.x + threadIdx.x; idx < N2 * DMODEL;
         idx += gridDim.x * blockDim.x) {
        int j = idx >> 11;
        int d = idx & 2047;
        int n = j & 31;
        float sre = g_par[128 + n], sim = g_par[160 + n];
        float br = Bre[n * DMODEL + d], bi = Bim[n * DMODEL + d];
        float v = (j < 32) ? (sre * br - sim * bi) : (sre * bi + sim * br);
        uint16_t h, l;
        cvt_hl(v, h, l);
        g_W1h[idx] = *(__nv_bfloat16*)&h;
        g_W1l[idx] = *(__nv_bfloat16*)&l;
    }
}

// g_W2h/l [d][j]
__global__ void k_w2(const float* __restrict__ Cre, const float* __restrict__ Cim) {
    for (int idx = blockIdx.x * blockDim.x + threadIdx.x; idx < DMODEL * N2;
         idx += gridDim.x * blockDim.x) {
        int d = idx >> 6;
        int j = idx & 63;
        float v = (j < 32) ? (2.f * Cre[d * HALF + j])
                           : (-2.f * Cim[d * HALF + (j - 32)]);
        uint16_t h, l;
        cvt_hl(v, h, l);
        g_W2h[idx] = *(__nv_bfloat16*)&h;
        g_W2l[idx] = *(__nv_bfloat16*)&l;
    }
}

// ---------------- GEMM1: Bu[16384,64] = u @ W1^T  (bf16x3 HMMA) ----------------
// 256 thr, BM=128, BN=64, K_TILE=64 (8 panels), 32 tiles; warp = m32 x n32.
__global__ __launch_bounds__(256) void k_gemm1(const float* __restrict__ u) {
    extern __shared__ char smem[];
    char* pAh = smem + OFF_AH;
    char* pAl = smem + OFF_AL;
    char* pBh = smem + OFF_BH;
    char* pBl = smem + OFF_BL;
    int tid = threadIdx.x;
    int lane = tid & 31, g = lane >> 2, tig = lane & 3;
    int w = tid >> 5, wm = w >> 1, wn = w & 1;
    int m0 = blockIdx.x * 128;

    float acc[2][4][4];
    #pragma unroll
    for (int mt = 0; mt < 2; ++mt)
        #pragma unroll
        for (int nt = 0; nt < 4; ++nt)
            #pragma unroll
            for (int i = 0; i < 4; ++i) acc[mt][nt][i] = 0.f;

    float4 ru[4][2];
    uint4 rwh[2], rwl[2];

    // prefetch tile 0
    #pragma unroll
    for (int i = 0; i < 4; ++i) {
        int task = tid + 256 * i;
        int row = task >> 3, kp = task & 7;
        const float* s = u + (size_t)(m0 + row) * DMODEL + kp * 8;
        ru[i][0] = *(const float4*)s;
        ru[i][1] = *(const float4*)(s + 4);
    }
    #pragma unroll
    for (int i = 0; i < 2; ++i) {
        int task = tid + 256 * i;
        int n = task >> 3, kp = task & 7;
        size_t off = ((size_t)n * DMODEL + kp * 8) * 2;
        rwh[i] = *(const uint4*)((const char*)g_W1h + off);
        rwl[i] = *(const uint4*)((const char*)g_W1l + off);
    }

    for (int kt = 0; kt < DMODEL / 64; ++kt) {
        __syncthreads();
        // STS staged tile
        #pragma unroll
        for (int i = 0; i < 4; ++i) {
            int task = tid + 256 * i;
            int row = task >> 3, kp = task & 7;
            uint4 h, l;
            cvt8(ru[i][0], ru[i][1], h, l);
            int off = kp * A_PANEL + (row ^ kp) * 16;
            *(uint4*)(pAh + off) = h;
            *(uint4*)(pAl + off) = l;
        }
        #pragma unroll
        for (int i = 0; i < 2; ++i) {
            int task = tid + 256 * i;
            int n = task >> 3, kp = task & 7;
            int off = kp * B_PANEL + (n ^ kp) * 16;
            *(uint4*)(pBh + off) = rwh[i];
            *(uint4*)(pBl + off) = rwl[i];
        }
        __syncthreads();
        // prefetch next tile
        if (kt + 1 < DMODEL / 64) {
            int kb = (kt + 1) * 64;
            #pragma unroll
            for (int i = 0; i < 4; ++i) {
                int task = tid + 256 * i;
                int row = task >> 3, kp = task & 7;
                const float* s = u + (size_t)(m0 + row) * DMODEL + kb + kp * 8;
                ru[i][0] = *(const float4*)s;
                ru[i][1] = *(const float4*)(s + 4);
            }
            #pragma unroll
            for (int i = 0; i < 2; ++i) {
                int task = tid + 256 * i;
                int n = task >> 3, kp = task & 7;
                size_t off = ((size_t)n * DMODEL + kb + kp * 8) * 2;
                rwh[i] = *(const uint4*)((const char*)g_W1h + off);
                rwl[i] = *(const uint4*)((const char*)g_W1l + off);
            }
        }
        // compute 4 k16 steps
        #pragma unroll
        for (int ks = 0; ks < 4; ++ks) {
            int p = ks * 2;
            uint32_t ah0[4], ah1[4], al0[4], al1[4];
            ldA(pAh, p, wm * 32,      g, tig, ah0);
            ldA(pAh, p, wm * 32 + 16, g, tig, ah1);
            ldA(pAl, p, wm * 32,      g, tig, al0);
            ldA(pAl, p, wm * 32 + 16, g, tig, al1);
            #pragma unroll
            for (int nt = 0; nt < 4; ++nt) {
                int nb = wn * 32 + nt * 8;
                uint32_t bh[2], bl[2];
                ldB(pBh, p, nb, g, tig, bh);
                ldB(pBl, p, nb, g, tig, bl);
                mma16816(acc[0][nt], ah0, bh);
                mma16816(acc[0][nt], ah0, bl);
                mma16816(acc[0][nt], al0, bh);
                mma16816(acc[1][nt], ah1, bh);
                mma16816(acc[1][nt], ah1, bl);
                mma16816(acc[1][nt], al1, bh);
            }
        }
    }
    // epilogue -> g_Bu
    #pragma unroll
    for (int mt = 0; mt < 2; ++mt) {
        int r0 = m0 + wm * 32 + mt * 16 + g;
        #pragma unroll
        for (int nt = 0; nt < 4; ++nt) {
            int col = wn * 32 + nt * 8 + 2 * tig;
            float* a = acc[mt][nt];
            *(float2*)(g_Bu + (size_t)r0 * N2 + col)       = make_float2(a[0], a[1]);
            *(float2*)(g_Bu + (size_t)(r0 + 8) * N2 + col) = make_float2(a[2], a[3]);
        }
    }
}

// ---------------- scan (fp32, unchanged) ----------------
__global__ void k_scan_local() {
    int w = (blockIdx.x * blockDim.x + threadIdx.x) >> 5;
    int lane = threadIdx.x & 31;
    int b = w >> 6, c = w & (NCHUNK - 1);
    float lbr = g_par[lane], lbi = g_par[32 + lane];
    float xr = 0.f, xi = 0.f;
    size_t base = ((size_t)b * SEQL + (size_t)c * CHUNK) * N2;
    for (int i = 0; i < CHUNK; ++i) {
        size_t off = base + (size_t)i * N2;
        float br = g_Bu[off + lane];
        float bi = g_Bu[off + 32 + lane];
        float nr = fmaf(lbr, xr, fmaf(-lbi, xi, br));
        float ni = fmaf(lbr, xi, fmaf( lbi, xr, bi));
        g_Bu[off + lane]      = nr;
        g_Bu[off + 32 + lane] = ni;
        xr = nr; xi = ni;
    }
    int co = (b * NCHUNK + c) * N2;
    g_carry[co + lane] = xr;
    g_carry[co + 32 + lane] = xi;
}

__global__ void k_scan_prefix() {
    int w = threadIdx.x >> 5;
    int lane = threadIdx.x & 31;
    float lbSr = g_par[64 + lane], lbSi = g_par[96 + lane];
    float Pr = 0.f, Pi = 0.f;
    for (int c = 0; c < NCHUNK; ++c) {
        int o = (w * NCHUNK + c) * N2;
        g_pref[o + lane] = Pr;
        g_pref[o + 32 + lane] = Pi;
        float cr = g_carry[o + lane];
        float ci = g_carry[o + 32 + lane];
        float nr = fmaf(lbSr, Pr, fmaf(-lbSi, Pi, cr));
        float ni = fmaf(lbSr, Pi, fmaf( lbSi, Pr, ci));
        Pr = nr; Pi = ni;
    }
}

__global__ void k_scan_fix() {
    int w = (blockIdx.x * blockDim.x + threadIdx.x) >> 5;
    int lane = threadIdx.x & 31;
    int b = w >> 6, c = w & (NCHUNK - 1);
    float lbr = g_par[lane], lbi = g_par[32 + lane];
    int po = (b * NCHUNK + c) * N2;
    float Pr = g_pref[po + lane], Pi = g_pref[po + 32 + lane];
    float pr = lbr, pi = lbi;
    size_t base = ((size_t)b * SEQL + (size_t)c * CHUNK) * N2;
    for (int i = 0; i < CHUNK; ++i) {
        size_t off = base + (size_t)i * N2;
        float ar = pr * Pr - pi * Pi;
        float ai = pr * Pi + pi * Pr;
        g_Bu[off + lane]      += ar;
        g_Bu[off + 32 + lane] += ai;
        float npr = pr * lbr - pi * lbi;
        float npi = pr * lbi + pi * lbr;
        pr = npr; pi = npi;
    }
}

// ---------------- GEMM2: y = X @ W2 + D.u  (bf16x3 HMMA) ----------------
// 256 thr, BM=128, BN=64, K=64 single tile; warp = m32 x n32.
__global__ __launch_bounds__(256) void k_gemm2(const float* __restrict__ u,
                                               const float* __restrict__ Dv,
                                               float* __restrict__ y) {
    extern __shared__ char smem[];
    char* pAh = smem + OFF_AH;
    char* pAl = smem + OFF_AL;
    char* pBh = smem + OFF_BH;
    char* pBl = smem + OFF_BL;
    int tid = threadIdx.x;
    int lane = tid & 31, g = lane >> 2, tig = lane & 3;
    int w = tid >> 5, wm = w >> 1, wn = w & 1;
    int n0 = blockIdx.x * 64;
    int m0 = blockIdx.y * 128;

    // stage A = X (fp32 -> bf16 hi/lo)
    #pragma unroll
    for (int i = 0; i < 4; ++i) {
        int task = tid + 256 * i;
        int row = task >> 3, kp = task & 7;
        const float* s = g_Bu + (size_t)(m0 + row) * N2 + kp * 8;
        uint4 h, l;
        cvt8(*(const float4*)s, *(const float4*)(s + 4), h, l);
        int off = kp * A_PANEL + (row ^ kp) * 16;
        *(uint4*)(pAh + off) = h;
        *(uint4*)(pAl + off) = l;
    }
    // stage B = W2 rows n0..n0+63 (already bf16)
    #pragma unroll
    for (int i = 0; i < 2; ++i) {
        int task = tid + 256 * i;
        int n = task >> 3, kp = task & 7;
        size_t goff = ((size_t)(n0 + n) * N2 + kp * 8) * 2;
        int off = kp * B_PANEL + (n ^ kp) * 16;
        *(uint4*)(pBh + off) = *(const uint4*)((const char*)g_W2h + goff);
        *(uint4*)(pBl + off) = *(const uint4*)((const char*)g_W2l + goff);
    }
    __syncthreads();

    float acc[2][4][4];
    #pragma unroll
    for (int mt = 0; mt < 2; ++mt)
        #pragma unroll
        for (int nt = 0; nt < 4; ++nt)
            #pragma unroll
            for (int i = 0; i < 4; ++i) acc[mt][nt][i] = 0.f;

    #pragma unroll
    for (int ks = 0; ks < 4; ++ks) {
        int p = ks * 2;
        uint32_t ah0[4], ah1[4], al0[4], al1[4];
        ldA(pAh, p, wm * 32,      g, tig, ah0);
        ldA(pAh, p, wm * 32 + 16, g, tig, ah1);
        ldA(pAl, p, wm * 32,      g, tig, al0);
        ldA(pAl, p, wm * 32 + 16, g, tig, al1);
        #pragma unroll
        for (int nt = 0; nt < 4; ++nt) {
            int nb = wn * 32 + nt * 8;
            uint32_t bh[2], bl[2];
            ldB(pBh, p, nb, g, tig, bh);
            ldB(pBl, p, nb, g, tig, bl);
            mma16816(acc[0][nt], ah0, bh);
            mma16816(acc[0][nt], ah0, bl);
            mma16816(acc[0][nt], al0, bh);
            mma16816(acc[1][nt], ah1, bh);
            mma16816(acc[1][nt], ah1, bl);
            mma16816(acc[1][nt], al1, bh);
        }
    }

    // epilogue: y = acc + D*u
    #pragma unroll
    for (int nt = 0; nt < 4; ++nt) {
        int col = n0 + wn * 32 + nt * 8 + 2 * tig;
        float2 dv = *(const float2*)(Dv + col);
        #pragma unroll
        for (int mt = 0; mt < 2; ++mt) {
            int r0 = m0 + wm * 32 + mt * 16 + g;
            float* a = acc[mt][nt];
            size_t o0 = (size_t)r0 * DMODEL + col;
            size_t o1 = o0 + (size_t)8 * DMODEL;
            float2 u0 = *(const float2*)(u + o0);
            float2 u1 = *(const float2*)(u + o1);
            *(float2*)(y + o0) = make_float2(a[0] + dv.x * u0.x, a[1] + dv.y * u0.y);
            *(float2*)(y + o1) = make_float2(a[2] + dv.x * u1.x, a[3] + dv.y * u1.y);
        }
    }
}

// ---------------- launch ----------------
extern "C" void kernel_launch(void* const* d_in, const int* in_sizes, int n_in,
                              void* d_out, int out_size) {
    const float* u    = (const float*)d_in[0];
    const float* Lur  = (const float*)d_in[1];
    const float* Lim  = (const float*)d_in[2];
    const float* Bre  = (const float*)d_in[3];
    const float* Bim  = (const float*)d_in[4];
    const float* Cre  = (const float*)d_in[5];
    const float* Cim  = (const float*)d_in[6];
    const float* Dv   = (const float*)d_in[7];
    const float* logD = (const float*)d_in[8];
    float* y = (float*)d_out;

    cudaFuncSetAttribute(k_gemm1, cudaFuncAttributeMaxDynamicSharedMemorySize,
                         SMEM_BYTES);
    cudaFuncSetAttribute(k_gemm2, cudaFuncAttributeMaxDynamicSharedMemorySize,
                         SMEM_BYTES);

    k_params<<<1, 32>>>(Lur, Lim, logD);
    k_w1<<<128, 256>>>(Bre, Bim);
    k_w2<<<128, 256>>>(Cre, Cim);
    k_gemm1<<<MTOT / 128, 256, SMEM_BYTES>>>(u);
    k_scan_local<<<(BATCH * NCHUNK) / 4, 128>>>();
    k_scan_prefix<<<1, BATCH * 32>>>();
    k_scan_fix<<<(BATCH * NCHUNK) / 4, 128>>>();
    k_gemm2<<<dim3(DMODEL / 64, MTOT / 128), 256, SMEM_BYTES>>>(u, Dv, y);
}